// round 1
// baseline (speedup 1.0000x reference)
#include <cuda_runtime.h>
#include <cstdint>

#define BS   64
#define NQ   3000
#define NC   256
#define FH   100
#define FW   100
#define TOPK 1500

// Scratch for per-(b,q) scores (no cudaMalloc allowed).
__device__ float g_scores[BS * NQ];

// ---------------------------------------------------------------------------
// Kernel 1: scores[b,q] = max over NC=256 classes. One warp per row.
// Each lane: 2x float4 loads (512B/warp/load, fully coalesced), warp shfl max.
// ---------------------------------------------------------------------------
__global__ __launch_bounds__(256) void scores_kernel(const float* __restrict__ cls) {
    int warp_global = (blockIdx.x * blockDim.x + threadIdx.x) >> 5;
    int lane = threadIdx.x & 31;
    if (warp_global >= BS * NQ) return;

    const float4* row = reinterpret_cast<const float4*>(cls + (size_t)warp_global * NC);
    float4 a = row[lane];
    float4 b = row[lane + 32];
    float m = fmaxf(fmaxf(fmaxf(a.x, a.y), fmaxf(a.z, a.w)),
                    fmaxf(fmaxf(b.x, b.y), fmaxf(b.z, b.w)));
#pragma unroll
    for (int o = 16; o; o >>= 1)
        m = fmaxf(m, __shfl_xor_sync(0xFFFFFFFFu, m, o));
    if (lane == 0) g_scores[warp_global] = m;
}

// Monotone float -> uint key (total order matches float compare for finite vals)
__device__ __forceinline__ unsigned f2key(float f) {
    unsigned u = __float_as_uint(f);
    return u ^ ((u >> 31) ? 0xFFFFFFFFu : 0x80000000u);
}

// ---------------------------------------------------------------------------
// Kernel 2: per-batch fused top-k selection + rectangle-union mask paint.
// One block per batch, 1024 threads.
// ---------------------------------------------------------------------------
__global__ __launch_bounds__(1024) void mask_kernel(const float* __restrict__ coord,
                                                    const int*   __restrict__ vfs,
                                                    float*       __restrict__ out) {
    const int b    = blockIdx.x;
    const int tid  = threadIdx.x;
    const int lane = tid & 31;
    const int wid  = tid >> 5;

    __shared__ unsigned s_red[33];        // block reductions
    __shared__ unsigned s_woff[32];       // scan warp offsets
    __shared__ unsigned s_lyry[TOPK];     // packed (ly | ry<<16)
    __shared__ unsigned s_m[4][TOPK];     // column bitmasks (4 x u32 = 128 bits)
    __shared__ unsigned s_bitmap[FH][4];  // row coverage bitmaps
    __shared__ int      s_nrect;

    // ---- init shared state ----
    if (tid == 0) s_nrect = 0;
    for (int i = tid; i < FH * 4; i += 1024)
        (&s_bitmap[0][0])[i] = 0u;

    // ---- load keys: 3 contiguous queries per thread ----
    unsigned k[3];
#pragma unroll
    for (int j = 0; j < 3; j++) {
        int q = tid * 3 + j;
        k[j] = (q < NQ) ? f2key(g_scores[b * NQ + q]) : 0u;
    }

    // block-wide count of keys >= x (x >= 1 so invalid keys(=0) never count)
    auto block_count_ge = [&](unsigned x) -> unsigned {
        unsigned c = 0;
#pragma unroll
        for (int j = 0; j < 3; j++) c += (k[j] >= x);
#pragma unroll
        for (int o = 16; o; o >>= 1) c += __shfl_down_sync(0xFFFFFFFFu, c, o);
        __syncthreads();                 // protect s_red reuse across calls
        if (lane == 0) s_red[wid] = c;
        __syncthreads();
        if (tid < 32) {
            unsigned v = s_red[lane];
#pragma unroll
            for (int o = 16; o; o >>= 1) v += __shfl_down_sync(0xFFFFFFFFu, v, o);
            if (lane == 0) s_red[32] = v;
        }
        __syncthreads();
        return s_red[32];
    };

    // ---- binary search for T = max{x : count_ge(x) >= TOPK} ----
    unsigned lo = 0u, hi = 0xFFFFFFFFu;
    while (lo < hi) {
        unsigned mid = lo + ((hi - lo) >> 1) + 1u;
        unsigned c = block_count_ge(mid);
        if (c >= TOPK) lo = mid; else hi = mid - 1u;
    }
    const unsigned T = lo;
    const unsigned cnt_gt  = (T == 0xFFFFFFFFu) ? 0u : block_count_ge(T + 1u);
    const unsigned need_eq = TOPK - cnt_gt;

    // ---- exclusive scan of (#keys == T) per thread, for index-order ties ----
    unsigned e = 0;
#pragma unroll
    for (int j = 0; j < 3; j++) e += (k[j] == T);
    unsigned inc = e;
#pragma unroll
    for (int o = 1; o < 32; o <<= 1) {
        unsigned v = __shfl_up_sync(0xFFFFFFFFu, inc, o);
        if (lane >= o) inc += v;
    }
    if (lane == 31) s_woff[wid] = inc;
    __syncthreads();
    if (tid < 32) {
        unsigned v = s_woff[lane];
        unsigned i2 = v;
#pragma unroll
        for (int o = 1; o < 32; o <<= 1) {
            unsigned u = __shfl_up_sync(0xFFFFFFFFu, i2, o);
            if (lane >= o) i2 += u;
        }
        s_woff[lane] = i2 - v;           // exclusive warp offsets
    }
    __syncthreads();
    const unsigned my_off = s_woff[wid] + (inc - e);

    // ---- build rects for selected queries ----
    const float fvh = (float)vfs[b * 2 + 0];
    const float fvw = (float)vfs[b * 2 + 1];
    unsigned cum = 0;
#pragma unroll
    for (int j = 0; j < 3; j++) {
        int q = tid * 3 + j;
        bool sel = false;
        if (q < NQ) {
            if (k[j] > T) sel = true;
            else if (k[j] == T) { sel = (my_off + cum < need_eq); cum++; }
        }
        if (sel) {
            float4 c4 = *reinterpret_cast<const float4*>(coord + ((size_t)b * NQ + q) * 4);
            // Non-contracted IEEE ops to match XLA bit-for-bit at floor boundaries
            float hw = __fmul_rn(0.5f, c4.z);
            float hh = __fmul_rn(0.5f, c4.w);
            float x0 = __fsub_rn(c4.x, hw);
            float y0 = __fsub_rn(c4.y, hh);
            float x1 = __fadd_rn(c4.x, hw);
            float y1 = __fadd_rn(c4.y, hh);
            int lx = (int)floorf(__fmul_rn(x0, fvh));
            int ly = (int)floorf(__fmul_rn(y0, fvw));
            int rx = (int)floorf(__fmul_rn(x1, fvh));
            int ry = (int)floorf(__fmul_rn(y1, fvw));
            int lc  = max(lx, 0), rc  = min(rx, FW);
            int lyc = max(ly, 0), ryc = min(ry, FH);
            if (ryc < lyc) ryc = lyc;    // empty row range
            int slot = atomicAdd(&s_nrect, 1);
            s_lyry[slot] = (unsigned)lyc | ((unsigned)ryc << 16);
#pragma unroll
            for (int w = 0; w < 4; w++) {
                int l = min(max(lc - 32 * w, 0), 32);
                int h = min(max(rc - 32 * w, 0), 32);
                unsigned m = 0;
                if (h > l) {
                    unsigned mh = (h == 32) ? 0xFFFFFFFFu : ((1u << h) - 1u);
                    m = mh & ~((1u << l) - 1u);   // l < 32 guaranteed here
                }
                s_m[w][slot] = m;
            }
        }
    }
    __syncthreads();

    // ---- paint: thread = (row = tid&127, slice = tid>>7); slices stride rects
    // slice is warp-uniform -> rect reads are smem broadcasts.
    const int nrect = s_nrect;
    {
        int row   = tid & 127;
        int slice = tid >> 7;
        if (row < FH) {
            unsigned r0 = 0, r1 = 0, r2 = 0, r3 = 0;
            for (int i = slice; i < nrect; i += 8) {
                unsigned lr = s_lyry[i];
                int ly = (int)(lr & 0xFFFFu), ry = (int)(lr >> 16);
                if (row >= ly && row < ry) {
                    r0 |= s_m[0][i]; r1 |= s_m[1][i];
                    r2 |= s_m[2][i]; r3 |= s_m[3][i];
                }
            }
            if (r0) atomicOr(&s_bitmap[row][0], r0);
            if (r1) atomicOr(&s_bitmap[row][1], r1);
            if (r2) atomicOr(&s_bitmap[row][2], r2);
            if (r3) atomicOr(&s_bitmap[row][3], r3);
        }
    }
    __syncthreads();

    // ---- write output: masked (-1e20) unless covered && !padding ----
    const int vh = vfs[b * 2 + 0];
    const int vw = vfs[b * 2 + 1];
    float* obase = out + (size_t)b * FH * FW;
    for (int idx = tid; idx < FH * FW; idx += 1024) {
        int h = idx / FW;
        int w = idx - h * FW;
        bool cov = (s_bitmap[h][w >> 5] >> (w & 31)) & 1u;
        bool pad = (h >= vh) || (w >= vw);
        obase[idx] = (cov && !pad) ? 0.0f : -1e20f;
    }
}

// ---------------------------------------------------------------------------
extern "C" void kernel_launch(void* const* d_in, const int* in_sizes, int n_in,
                              void* d_out, int out_size) {
    const float* coord = (const float*)d_in[0];  // (BS, NQ, 4) f32
    const float* cls   = (const float*)d_in[1];  // (BS, NQ, NC) f32
    const int*   vfs   = (const int*)d_in[2];    // (BS, 2) i32
    float* out = (float*)d_out;                  // (BS, FH*FW) f32

    int nwarps = BS * NQ;                        // one warp per (b,q) row
    int threads = 256;
    int blocks = (nwarps * 32 + threads - 1) / threads;  // 24000
    scores_kernel<<<blocks, threads>>>(cls);
    mask_kernel<<<BS, 1024>>>(coord, vfs, out);
}